// round 11
// baseline (speedup 1.0000x reference)
#include <cuda_runtime.h>
#include <cuda_fp16.h>
#include <cstdint>
#include <math_constants.h>

// ---------------- problem constants ----------------
#define M_TOTAL 16384
#define DIM     128
#define NCODES  10000
#define NPAD2   10240                 // 40 tiles x 256
#define NTILES  40
#define NBUFS   (NTILES * 2)          // 80 buffers: per tile kind0=Ch, kind1=Cl
#define BUF_U32 16384                 // 256 N x 8 k16-steps = 64 KB
#define SLICE_U32 4096                // per-wn slice: 16 KB
#define MTILE   128
#define RESCALE 4.8828125e-4f         // 1/2048

// smem: A fragments (Xh|Xl' planes) 65536 B, then Ch buf 65536 + Cl buf 65536
#define A_BYTES  65536
#define B_BYTES  65536
#define SMEM_TOTAL (A_BYTES + 2 * B_BYTES)   // 196608

// ---------------- device scratch ----------------
__device__ float    g_cnorm[NPAD2];                      // ||c||^2 (+INF pad)
__device__ float    g_loss;
__device__ float    g_ctr[(size_t)NPAD2 * DIM];          // exact fp32 codebook [n][k]
__device__ uint32_t g_Bu[(size_t)NBUFS * BUF_U32];       // packed fp16 B-frag stream

// ---------------- helpers ----------------
__device__ __forceinline__ uint32_t smem_u32(const void* p) {
    uint32_t a;
    asm("{ .reg .u64 t; cvta.to.shared.u64 t, %1; cvt.u32.u64 %0, t; }"
        : "=r"(a) : "l"(p));
    return a;
}
__device__ __forceinline__ void cpa16(uint32_t dst, const void* src) {
    asm volatile("cp.async.cg.shared.global [%0], [%1], 16;" :: "r"(dst), "l"(src));
}
__device__ __forceinline__ void cpa_commit() {
    asm volatile("cp.async.commit_group;" ::: "memory");
}
__device__ __forceinline__ void pair_bar(int wn) {
    asm volatile("bar.sync %0, 64;" :: "r"(wn + 1) : "memory");
}
__device__ __forceinline__ uint32_t h2pair(float a, float b) {
    __half2 h = __floats2half2_rn(a, b);
    return *(uint32_t*)&h;
}
__device__ __forceinline__ uint32_t l2pair(float a, float b) {   // scaled residual
    float ah = __half2float(__float2half_rn(a));
    float bh = __half2float(__float2half_rn(b));
    return h2pair((a - ah) * 2048.0f, (b - bh) * 2048.0f);
}
__device__ __forceinline__ void mma_f16(float* c, const uint4& a,
                                        uint32_t b0, uint32_t b1) {
    asm volatile(
        "mma.sync.aligned.m16n8k16.row.col.f32.f16.f16.f32 "
        "{%0,%1,%2,%3}, {%4,%5,%6,%7}, {%8,%9}, {%0,%1,%2,%3};"
        : "+f"(c[0]), "+f"(c[1]), "+f"(c[2]), "+f"(c[3])
        : "r"(a.x), "r"(a.y), "r"(a.z), "r"(a.w), "r"(b0), "r"(b1));
}

// one full-K pass (8 k16-steps): warp tile 64M x 64N; Bsl = this pair's 16KB slice
__device__ __forceinline__ void do_pass(float (&acc)[4][8][4], const char* As,
                                        const char* Bsl, int plane, int mw, int l) {
    #pragma unroll
    for (int s = 0; s < 8; ++s) {
        uint4 a[4];
        #pragma unroll
        for (int mt = 0; mt < 4; ++mt)
            a[mt] = *(const uint4*)(As +
                ((size_t)((plane * 64 + s * 8 + mw * 4 + mt) * 32 + l)) * 16);
        uint4 b[4];
        #pragma unroll
        for (int jp = 0; jp < 4; ++jp)
            b[jp] = *(const uint4*)(Bsl + ((size_t)((s * 4 + jp) * 32 + l)) * 16);
        #pragma unroll
        for (int mt = 0; mt < 4; ++mt)
            #pragma unroll
            for (int jp = 0; jp < 4; ++jp) {
                mma_f16(acc[mt][2 * jp],     a[mt], b[jp].x, b[jp].y);
                mma_f16(acc[mt][2 * jp + 1], a[mt], b[jp].z, b[jp].w);
            }
    }
}

// ---------------- kernel 0: init norms / loss ----------------
__global__ void init_kernel() {
    int j = blockIdx.x * blockDim.x + threadIdx.x;
    if (j == 0) g_loss = 0.0f;
    if (j < NPAD2) g_cnorm[j] = (j < NCODES) ? 0.0f : CUDART_INF_F;
}

// ---------------- kernel 1: transpose codebook (exact fp32) + norms ------------
__global__ void trans_kernel(const float* __restrict__ cm) {
    __shared__ float t[32][33], ps[8][33];
    int n0 = blockIdx.x * 32, k0 = blockIdx.y * 32;
    int tx = threadIdx.x, ty = threadIdx.y;
    float acc = 0.0f;
    for (int i = ty; i < 32; i += 8) {
        int n = n0 + tx;
        float v = (n < NCODES) ? cm[(size_t)(k0 + i) * NCODES + n] : 0.0f;
        t[tx][i] = v;
        acc = fmaf(v, v, acc);
    }
    ps[ty][tx] = acc;
    __syncthreads();
    for (int i = ty; i < 32; i += 8)
        g_ctr[(size_t)(n0 + i) * DIM + k0 + tx] = t[i][tx];
    if (ty == 0) {
        float s = 0.0f;
        #pragma unroll
        for (int y = 0; y < 8; ++y) s += ps[y][tx];
        if (n0 + tx < NCODES) atomicAdd(&g_cnorm[n0 + tx], s);
    }
}

// ---------------- kernel 2: pack codebook into fp16 B-fragment stream ----------
// u32 id bits (LSB first): r2(2) | l(5) | jp(2) | s(3) | wn(2) | b(7)
// buffer b = tile*2 + kind ; kind 0 -> Ch ; kind 1 -> Cl' (scaled residual)
// element: n = tile*256 + wn*64 + (jp*2 + (r2>>1))*8 + (l>>2)
//          k = s*16 + (r2&1)*8 + 2*(l&3)   (pair covers k, k+1)
__global__ void pack_kernel(const float* __restrict__ cm) {
    size_t id = (size_t)blockIdx.x * 256 + threadIdx.x;   // 1,310,720
    int r2 = (int)(id & 3);
    int l  = (int)((id >> 2) & 31);
    int jp = (int)((id >> 7) & 3);
    int s  = (int)((id >> 9) & 7);
    int wn = (int)((id >> 12) & 3);
    int b  = (int)(id >> 14);
    int tile = b >> 1, kind = b & 1;
    int n  = tile * 256 + wn * 64 + (jp * 2 + (r2 >> 1)) * 8 + (l >> 2);
    int k  = s * 16 + (r2 & 1) * 8 + 2 * (l & 3);
    uint32_t o = 0u;
    if (n < NCODES) {
        float v0 = cm[(size_t)k * NCODES + n];
        float v1 = cm[(size_t)(k + 1) * NCODES + n];
        o = kind ? l2pair(v0, v1) : h2pair(v0, v1);
    }
    g_Bu[id] = o;
}

// ---------------- kernel 3: fp16-split HMMA GEMM, rescale trick, 64x64 tiles ---
__global__ void __launch_bounds__(256, 1)
vq_main_kernel(const float* __restrict__ inp, float* __restrict__ out) {
    extern __shared__ __align__(16) char smem[];
    char* As  = smem;
    char* Bst = smem + A_BYTES;                 // [Ch buf | Cl buf]
    float* fbd  = (float*)(smem + A_BYTES);
    int*   fbi  = (int*)  (smem + A_BYTES + 2048);
    int*   sbi  = (int*)  (smem + A_BYTES + 4096);
    float* wsum = (float*)(smem + A_BYTES + 4608);
    const float* cn = g_cnorm;

    const int tid = threadIdx.x;
    const int w   = tid >> 5;
    const int l   = tid & 31;
    const int mw  = w >> 2;          // 0..1: 64-sample half
    const int wn  = w & 3;           // 0..3: 64-code slice (pair id)
    const int pt  = mw * 32 + l;     // thread id within the pair (0..63)
    const int s0  = blockIdx.x * MTILE;

    // ---- stage A: fp16 fragments, plane0 = Xh, plane1 = Xl' (= (x-xh)*2048) ----
    #pragma unroll
    for (int it = 0; it < 8; ++it) {
        int u = it * 8 + w;                 // 0..63: s*8 + mtile
        int s = u >> 3, mtg = u & 7;
        int m0 = mtg * 16 + (l >> 2);
        int kb = s * 16 + 2 * (l & 3);
        const float* p0 = inp + (size_t)(s0 + m0) * DIM + kb;
        float2 v00 = *(const float2*)(p0);
        float2 v10 = *(const float2*)(p0 + 8 * DIM);
        float2 v01 = *(const float2*)(p0 + 8);
        float2 v11 = *(const float2*)(p0 + 8 * DIM + 8);
        uint4 h, lo;
        h.x  = h2pair(v00.x, v00.y);  h.y  = h2pair(v10.x, v10.y);
        h.z  = h2pair(v01.x, v01.y);  h.w  = h2pair(v11.x, v11.y);
        lo.x = l2pair(v00.x, v00.y);  lo.y = l2pair(v10.x, v10.y);
        lo.z = l2pair(v01.x, v01.y);  lo.w = l2pair(v11.x, v11.y);
        *(uint4*)(As + ((size_t)((      u) * 32 + l)) * 16) = h;
        *(uint4*)(As + ((size_t)((64 +  u) * 32 + l)) * 16) = lo;
    }
    __syncthreads();

    // pair-private slice bases
    const uint32_t bCh = smem_u32(Bst) + wn * (SLICE_U32 * 4);
    const uint32_t bCl = bCh + B_BYTES;
    const char* BslCh = Bst + (size_t)wn * (SLICE_U32 * 4);
    const char* BslCl = BslCh + B_BYTES;

    // ---- prologue: load Cl(0) then Ch(0) (Cl committed first = older group) ----
    #pragma unroll
    for (int i = 0; i < 16; ++i) {
        int idx = i * 64 + pt;
        cpa16(bCl + idx * 16, g_Bu + (size_t)1 * BUF_U32 + wn * SLICE_U32 + (size_t)idx * 4);
    }
    cpa_commit();
    #pragma unroll
    for (int i = 0; i < 16; ++i) {
        int idx = i * 64 + pt;
        cpa16(bCh + idx * 16, g_Bu + (size_t)0 * BUF_U32 + wn * SLICE_U32 + (size_t)idx * 4);
    }
    cpa_commit();

    float acc[4][8][4];
    #pragma unroll
    for (int mt = 0; mt < 4; ++mt)
        #pragma unroll
        for (int j = 0; j < 8; ++j)
            #pragma unroll
            for (int r = 0; r < 4; ++r) acc[mt][j][r] = 0.0f;

    float bd[8]; int bi[8];
    #pragma unroll
    for (int s = 0; s < 8; ++s) { bd[s] = CUDART_INF_F; bi[s] = 0; }

    #pragma unroll 1
    for (int t = 0; t < NTILES; ++t) {
        // -------- pass 1: Xh * (2048*Cl) --------
        asm volatile("cp.async.wait_group 1;" ::: "memory");   // Cl(t) landed
        pair_bar(wn);
        do_pass(acc, As, BslCl, 0, mw, l);
        pair_bar(wn);                                          // pair done with Cl
        if (t + 1 < NTILES) {
            #pragma unroll
            for (int i = 0; i < 16; ++i) {
                int idx = i * 64 + pt;
                cpa16(bCl + idx * 16,
                      g_Bu + (size_t)((t + 1) * 2 + 1) * BUF_U32 + wn * SLICE_U32 + (size_t)idx * 4);
            }
        }
        cpa_commit();

        // -------- pass 2: (2048*Xl) * Ch ; rescale ; pass 3: Xh * Ch --------
        asm volatile("cp.async.wait_group 1;" ::: "memory");   // Ch(t) landed
        pair_bar(wn);
        do_pass(acc, As, BslCh, 1, mw, l);
        #pragma unroll
        for (int mt = 0; mt < 4; ++mt)
            #pragma unroll
            for (int j = 0; j < 8; ++j)
                #pragma unroll
                for (int r = 0; r < 4; ++r) acc[mt][j][r] *= RESCALE;
        do_pass(acc, As, BslCh, 0, mw, l);
        pair_bar(wn);                                          // pair done with Ch
        if (t + 1 < NTILES) {
            #pragma unroll
            for (int i = 0; i < 16; ++i) {
                int idx = i * 64 + pt;
                cpa16(bCh + idx * 16,
                      g_Bu + (size_t)((t + 1) * 2) * BUF_U32 + wn * SLICE_U32 + (size_t)idx * 4);
            }
        }
        cpa_commit();

        // -------- tile epilogue: dist = ||c||^2 - 2*dot -> running argmin --------
        int tb = t * 256 + wn * 64;
        #pragma unroll
        for (int j = 0; j < 8; ++j) {
            int n0 = tb + j * 8 + 2 * (l & 3);
            float2 c2 = *(const float2*)(cn + n0);
            #pragma unroll
            for (int mt = 0; mt < 4; ++mt) {
                float d0 = fmaf(-2.0f, acc[mt][j][0], c2.x);
                float d1 = fmaf(-2.0f, acc[mt][j][1], c2.y);
                float d2 = fmaf(-2.0f, acc[mt][j][2], c2.x);
                float d3 = fmaf(-2.0f, acc[mt][j][3], c2.y);
                int slo = mt * 2, shi = mt * 2 + 1;
                if (d0 < bd[slo]) { bd[slo] = d0; bi[slo] = n0; }
                if (d1 < bd[slo]) { bd[slo] = d1; bi[slo] = n0 + 1; }
                if (d2 < bd[shi]) { bd[shi] = d2; bi[shi] = n0; }
                if (d3 < bd[shi]) { bd[shi] = d3; bi[shi] = n0 + 1; }
                #pragma unroll
                for (int r = 0; r < 4; ++r) acc[mt][j][r] = 0.0f;
            }
        }
    }

    // ---- reduce argmin across lanes sharing the same row (xor 1,2) ----
    #pragma unroll
    for (int s = 0; s < 8; ++s) {
        #pragma unroll
        for (int o = 1; o < 4; o <<= 1) {
            float od = __shfl_xor_sync(0xffffffffu, bd[s], o);
            int   oi = __shfl_xor_sync(0xffffffffu, bi[s], o);
            if (od < bd[s] || (od == bd[s] && oi < bi[s])) { bd[s] = od; bi[s] = oi; }
        }
    }
    asm volatile("cp.async.wait_group 0;" ::: "memory");
    __syncthreads();                  // B region reusable
    if ((l & 3) == 0) {
        #pragma unroll
        for (int s = 0; s < 8; ++s) {
            int mt = s >> 1, half = s & 1;
            int m = mw * 64 + mt * 16 + half * 8 + (l >> 2);
            fbd[wn * 128 + m] = bd[s];
            fbi[wn * 128 + m] = bi[s];
        }
    }
    __syncthreads();
    if (tid < 128) {
        float best = fbd[tid]; int bidx = fbi[tid];
        #pragma unroll
        for (int q = 1; q < 4; ++q) {
            float d = fbd[q * 128 + tid]; int i2 = fbi[q * 128 + tid];
            if (d < best || (d == best && i2 < bidx)) { best = d; bidx = i2; }
        }
        sbi[tid] = bidx;
    }
    __syncthreads();

    // ---- gather exact fp32 codes, write outputs, loss partial ----
    float lsum = 0.0f;
    #pragma unroll 4
    for (int rr = 0; rr < 64; ++rr) {
        int idx = rr * 256 + tid;
        int s = idx >> 7, k = idx & (DIM - 1);
        int c = sbi[s];
        float q = g_ctr[(size_t)c * DIM + k];
        float x = inp[(size_t)(s0 + s) * DIM + k];
        float d = q - x;
        out[(size_t)(s0 + s) * DIM + k] = x + d;
        lsum = fmaf(d, d, lsum);
    }
    #pragma unroll
    for (int o = 16; o > 0; o >>= 1) lsum += __shfl_xor_sync(0xffffffffu, lsum, o);
    if (l == 0) wsum[w] = lsum;
    __syncthreads();
    if (tid == 0) {
        float s = 0.0f;
        #pragma unroll
        for (int i = 0; i < 8; ++i) s += wsum[i];
        atomicAdd(&g_loss, s);
    }
}

// ---------------- kernel 4: loss = 1.25 * mean((q-x)^2) ----------------
__global__ void finalize_kernel(float* __restrict__ dst) {
    *dst = 1.25f * g_loss * (1.0f / (float)(M_TOTAL * DIM));
}

extern "C" void kernel_launch(void* const* d_in, const int* in_sizes, int n_in,
                              void* d_out, int out_size) {
    const float* inp = (const float*)d_in[0];
    const float* cm  = (const float*)d_in[1];
    if (n_in >= 2 && in_sizes[0] == DIM * NCODES && in_sizes[1] == M_TOTAL * DIM) {
        inp = (const float*)d_in[1];
        cm  = (const float*)d_in[0];
    }
    float* out = (float*)d_out;

    cudaFuncSetAttribute(vq_main_kernel,
                         cudaFuncAttributeMaxDynamicSharedMemorySize, SMEM_TOTAL);

    init_kernel<<<(NPAD2 + 255) / 256, 256>>>();
    trans_kernel<<<dim3(NPAD2 / 32, DIM / 32), dim3(32, 8)>>>(cm);
    pack_kernel<<<(int)(((size_t)NBUFS * BUF_U32) / 256), 256>>>(cm);
    vq_main_kernel<<<M_TOTAL / MTILE, 256, SMEM_TOTAL>>>(inp, out);
    if (out_size > M_TOTAL * DIM) {
        finalize_kernel<<<1, 1>>>(out + M_TOTAL * DIM);
    }
}

// round 16
// speedup vs baseline: 1.0643x; 1.0643x over previous
#include <cuda_runtime.h>
#include <cuda_fp16.h>
#include <cstdint>
#include <math_constants.h>

// ---------------- problem constants ----------------
#define M_TOTAL 16384
#define DIM     128
#define NCODES  10000
#define NPAD2   10240                 // 40 tiles x 256
#define NTILES  40
#define NBUFS   (NTILES * 2)          // 80 buffers: per tile kind0=Ch, kind1=Cl
#define BUF_U32 16384                 // 256 N x 8 k16-steps = 64 KB
#define SLICE_U32 2048                // per-wn slice: 8 KB (8 slices)
#define MTILE   128
#define THREADS 512
#define RESCALE 4.8828125e-4f         // 1/2048

// smem: A fragments (Xh|Xl' planes) 65536 B, then Ch buf 65536 + Cl buf 65536
#define A_BYTES  65536
#define B_BYTES  65536
#define SMEM_TOTAL (A_BYTES + 2 * B_BYTES)   // 196608

// ---------------- device scratch ----------------
__device__ float    g_cnorm[NPAD2];                      // ||c||^2 (+INF pad)
__device__ float    g_loss;
__device__ float    g_ctr[(size_t)NPAD2 * DIM];          // exact fp32 codebook [n][k]
__device__ uint32_t g_Bu[(size_t)NBUFS * BUF_U32];       // packed fp16 B-frag stream

// ---------------- helpers ----------------
__device__ __forceinline__ uint32_t smem_u32(const void* p) {
    uint32_t a;
    asm("{ .reg .u64 t; cvta.to.shared.u64 t, %1; cvt.u32.u64 %0, t; }"
        : "=r"(a) : "l"(p));
    return a;
}
__device__ __forceinline__ void cpa16(uint32_t dst, const void* src) {
    asm volatile("cp.async.cg.shared.global [%0], [%1], 16;" :: "r"(dst), "l"(src));
}
__device__ __forceinline__ void cpa_commit() {
    asm volatile("cp.async.commit_group;" ::: "memory");
}
__device__ __forceinline__ void pair_bar(int wn) {
    asm volatile("bar.sync %0, 64;" :: "r"(wn + 1) : "memory");
}
__device__ __forceinline__ uint32_t h2pair(float a, float b) {
    __half2 h = __floats2half2_rn(a, b);
    return *(uint32_t*)&h;
}
__device__ __forceinline__ uint32_t l2pair(float a, float b) {   // scaled residual
    float ah = __half2float(__float2half_rn(a));
    float bh = __half2float(__float2half_rn(b));
    return h2pair((a - ah) * 2048.0f, (b - bh) * 2048.0f);
}
__device__ __forceinline__ void mma_f16(float* c, const uint4& a,
                                        uint32_t b0, uint32_t b1) {
    asm volatile(
        "mma.sync.aligned.m16n8k16.row.col.f32.f16.f16.f32 "
        "{%0,%1,%2,%3}, {%4,%5,%6,%7}, {%8,%9}, {%0,%1,%2,%3};"
        : "+f"(c[0]), "+f"(c[1]), "+f"(c[2]), "+f"(c[3])
        : "r"(a.x), "r"(a.y), "r"(a.z), "r"(a.w), "r"(b0), "r"(b1));
}

// one full-K pass (8 k16-steps): warp tile 64M x 32N; Bsl = this pair's 8KB slice
__device__ __forceinline__ void do_pass(float (&acc)[4][4][4], const char* As,
                                        const char* Bsl, int plane, int mw, int l) {
    #pragma unroll
    for (int s = 0; s < 8; ++s) {
        uint4 a[4];
        #pragma unroll
        for (int mt = 0; mt < 4; ++mt)
            a[mt] = *(const uint4*)(As +
                ((size_t)((plane * 64 + s * 8 + mw * 4 + mt) * 32 + l)) * 16);
        uint4 b0 = *(const uint4*)(Bsl + ((size_t)((s * 2 + 0) * 32 + l)) * 16);
        uint4 b1 = *(const uint4*)(Bsl + ((size_t)((s * 2 + 1) * 32 + l)) * 16);
        #pragma unroll
        for (int mt = 0; mt < 4; ++mt) {
            mma_f16(acc[mt][0], a[mt], b0.x, b0.y);
            mma_f16(acc[mt][1], a[mt], b0.z, b0.w);
            mma_f16(acc[mt][2], a[mt], b1.x, b1.y);
            mma_f16(acc[mt][3], a[mt], b1.z, b1.w);
        }
    }
}

// ---------------- kernel 0: init norms / loss ----------------
__global__ void init_kernel() {
    int j = blockIdx.x * blockDim.x + threadIdx.x;
    if (j == 0) g_loss = 0.0f;
    if (j < NPAD2) g_cnorm[j] = (j < NCODES) ? 0.0f : CUDART_INF_F;
}

// ---------------- kernel 1: transpose codebook (exact fp32) + norms ------------
__global__ void trans_kernel(const float* __restrict__ cm) {
    __shared__ float t[32][33], ps[8][33];
    int n0 = blockIdx.x * 32, k0 = blockIdx.y * 32;
    int tx = threadIdx.x, ty = threadIdx.y;
    float acc = 0.0f;
    for (int i = ty; i < 32; i += 8) {
        int n = n0 + tx;
        float v = (n < NCODES) ? cm[(size_t)(k0 + i) * NCODES + n] : 0.0f;
        t[tx][i] = v;
        acc = fmaf(v, v, acc);
    }
    ps[ty][tx] = acc;
    __syncthreads();
    for (int i = ty; i < 32; i += 8)
        g_ctr[(size_t)(n0 + i) * DIM + k0 + tx] = t[i][tx];
    if (ty == 0) {
        float s = 0.0f;
        #pragma unroll
        for (int y = 0; y < 8; ++y) s += ps[y][tx];
        if (n0 + tx < NCODES) atomicAdd(&g_cnorm[n0 + tx], s);
    }
}

// ---------------- kernel 2: pack codebook into fp16 B-fragment stream ----------
// u32 id bits (LSB first): r2(2) | l(5) | j2(1) | s(3) | wn(3) | b(7)
// buffer b = tile*2 + kind ; kind 0 -> Ch ; kind 1 -> Cl' (scaled residual)
// element: n = tile*256 + wn*32 + (j2*2 + (r2>>1))*8 + (l>>2)
//          k = s*16 + (r2&1)*8 + 2*(l&3)   (pair covers k, k+1)
__global__ void pack_kernel(const float* __restrict__ cm) {
    size_t id = (size_t)blockIdx.x * 256 + threadIdx.x;   // 1,310,720
    int r2 = (int)(id & 3);
    int l  = (int)((id >> 2) & 31);
    int j2 = (int)((id >> 7) & 1);
    int s  = (int)((id >> 8) & 7);
    int wn = (int)((id >> 11) & 7);
    int b  = (int)(id >> 14);
    int tile = b >> 1, kind = b & 1;
    int n  = tile * 256 + wn * 32 + (j2 * 2 + (r2 >> 1)) * 8 + (l >> 2);
    int k  = s * 16 + (r2 & 1) * 8 + 2 * (l & 3);
    uint32_t o = 0u;
    if (n < NCODES) {
        float v0 = cm[(size_t)k * NCODES + n];
        float v1 = cm[(size_t)(k + 1) * NCODES + n];
        o = kind ? l2pair(v0, v1) : h2pair(v0, v1);
    }
    g_Bu[id] = o;
}

// ---------------- kernel 3: fp16-split HMMA GEMM, 512 thr, 8 pair pipelines ----
__global__ void __launch_bounds__(THREADS, 1)
vq_main_kernel(const float* __restrict__ inp, float* __restrict__ out) {
    extern __shared__ __align__(16) char smem[];
    char* As  = smem;
    char* Bst = smem + A_BYTES;                 // [Ch buf | Cl buf]
    float* fbd  = (float*)(smem + A_BYTES);             // 8*128 floats
    int*   fbi  = (int*)  (smem + A_BYTES + 4096);
    int*   sbi  = (int*)  (smem + A_BYTES + 8192);
    float* wsum = (float*)(smem + A_BYTES + 8704);
    const float* cn = g_cnorm;

    const int tid = threadIdx.x;
    const int w   = tid >> 5;
    const int l   = tid & 31;
    const int mw  = w >> 3;          // 0..1: 64-sample half
    const int wn  = w & 7;           // 0..7: 32-code slice (pair id)
    const int pt  = mw * 32 + l;     // thread id within the pair (0..63)
    const int s0  = blockIdx.x * MTILE;

    // ---- stage A: fp16 fragments, plane0 = Xh, plane1 = Xl' (= (x-xh)*2048) ----
    #pragma unroll
    for (int it = 0; it < 4; ++it) {
        int u = it * 16 + w;                // 0..63: s*8 + mtile
        int s = u >> 3, mtg = u & 7;
        int m0 = mtg * 16 + (l >> 2);
        int kb = s * 16 + 2 * (l & 3);
        const float* p0 = inp + (size_t)(s0 + m0) * DIM + kb;
        float2 v00 = *(const float2*)(p0);
        float2 v10 = *(const float2*)(p0 + 8 * DIM);
        float2 v01 = *(const float2*)(p0 + 8);
        float2 v11 = *(const float2*)(p0 + 8 * DIM + 8);
        uint4 h, lo;
        h.x  = h2pair(v00.x, v00.y);  h.y  = h2pair(v10.x, v10.y);
        h.z  = h2pair(v01.x, v01.y);  h.w  = h2pair(v11.x, v11.y);
        lo.x = l2pair(v00.x, v00.y);  lo.y = l2pair(v10.x, v10.y);
        lo.z = l2pair(v01.x, v01.y);  lo.w = l2pair(v11.x, v11.y);
        *(uint4*)(As + ((size_t)((      u) * 32 + l)) * 16) = h;
        *(uint4*)(As + ((size_t)((64 +  u) * 32 + l)) * 16) = lo;
    }
    __syncthreads();

    // pair-private slice bases (8 KB per wn per kind buffer)
    const uint32_t bCh = smem_u32(Bst) + wn * (SLICE_U32 * 4);
    const uint32_t bCl = bCh + B_BYTES;
    const char* BslCh = Bst + (size_t)wn * (SLICE_U32 * 4);
    const char* BslCl = BslCh + B_BYTES;

    // ---- prologue: load Cl(0) then Ch(0) (Cl committed first = older group) ----
    #pragma unroll
    for (int i = 0; i < 8; ++i) {
        int idx = i * 64 + pt;
        cpa16(bCl + idx * 16, g_Bu + (size_t)1 * BUF_U32 + wn * SLICE_U32 + (size_t)idx * 4);
    }
    cpa_commit();
    #pragma unroll
    for (int i = 0; i < 8; ++i) {
        int idx = i * 64 + pt;
        cpa16(bCh + idx * 16, g_Bu + (size_t)0 * BUF_U32 + wn * SLICE_U32 + (size_t)idx * 4);
    }
    cpa_commit();

    float acc[4][4][4];
    #pragma unroll
    for (int mt = 0; mt < 4; ++mt)
        #pragma unroll
        for (int j = 0; j < 4; ++j)
            #pragma unroll
            for (int r = 0; r < 4; ++r) acc[mt][j][r] = 0.0f;

    float bd[8]; int bi[8];
    #pragma unroll
    for (int s = 0; s < 8; ++s) { bd[s] = CUDART_INF_F; bi[s] = 0; }

    #pragma unroll 1
    for (int t = 0; t < NTILES; ++t) {
        // -------- pass 1: Xh * (2048*Cl) --------
        asm volatile("cp.async.wait_group 1;" ::: "memory");   // Cl(t) landed
        pair_bar(wn);
        do_pass(acc, As, BslCl, 0, mw, l);
        pair_bar(wn);                                          // pair done with Cl
        if (t + 1 < NTILES) {
            #pragma unroll
            for (int i = 0; i < 8; ++i) {
                int idx = i * 64 + pt;
                cpa16(bCl + idx * 16,
                      g_Bu + (size_t)((t + 1) * 2 + 1) * BUF_U32 + wn * SLICE_U32 + (size_t)idx * 4);
            }
        }
        cpa_commit();

        // -------- pass 2: (2048*Xl) * Ch ; rescale ; pass 3: Xh * Ch --------
        asm volatile("cp.async.wait_group 1;" ::: "memory");   // Ch(t) landed
        pair_bar(wn);
        do_pass(acc, As, BslCh, 1, mw, l);
        #pragma unroll
        for (int mt = 0; mt < 4; ++mt)
            #pragma unroll
            for (int j = 0; j < 4; ++j)
                #pragma unroll
                for (int r = 0; r < 4; ++r) acc[mt][j][r] *= RESCALE;
        do_pass(acc, As, BslCh, 0, mw, l);
        pair_bar(wn);                                          // pair done with Ch
        if (t + 1 < NTILES) {
            #pragma unroll
            for (int i = 0; i < 8; ++i) {
                int idx = i * 64 + pt;
                cpa16(bCh + idx * 16,
                      g_Bu + (size_t)((t + 1) * 2) * BUF_U32 + wn * SLICE_U32 + (size_t)idx * 4);
            }
        }
        cpa_commit();

        // -------- tile epilogue: dist = ||c||^2 - 2*dot -> running argmin --------
        int tb = t * 256 + wn * 32;
        #pragma unroll
        for (int j = 0; j < 4; ++j) {
            int n0 = tb + j * 8 + 2 * (l & 3);
            float2 c2 = *(const float2*)(cn + n0);
            #pragma unroll
            for (int mt = 0; mt < 4; ++mt) {
                float d0 = fmaf(-2.0f, acc[mt][j][0], c2.x);
                float d1 = fmaf(-2.0f, acc[mt][j][1], c2.y);
                float d2 = fmaf(-2.0f, acc[mt][j][2], c2.x);
                float d3 = fmaf(-2.0f, acc[mt][j][3], c2.y);
                int slo = mt * 2, shi = mt * 2 + 1;
                if (d0 < bd[slo]) { bd[slo] = d0; bi[slo] = n0; }
                if (d1 < bd[slo]) { bd[slo] = d1; bi[slo] = n0 + 1; }
                if (d2 < bd[shi]) { bd[shi] = d2; bi[shi] = n0; }
                if (d3 < bd[shi]) { bd[shi] = d3; bi[shi] = n0 + 1; }
                #pragma unroll
                for (int r = 0; r < 4; ++r) acc[mt][j][r] = 0.0f;
            }
        }
    }

    // ---- reduce argmin across lanes sharing the same row (xor 1,2) ----
    #pragma unroll
    for (int s = 0; s < 8; ++s) {
        #pragma unroll
        for (int o = 1; o < 4; o <<= 1) {
            float od = __shfl_xor_sync(0xffffffffu, bd[s], o);
            int   oi = __shfl_xor_sync(0xffffffffu, bi[s], o);
            if (od < bd[s] || (od == bd[s] && oi < bi[s])) { bd[s] = od; bi[s] = oi; }
        }
    }
    asm volatile("cp.async.wait_group 0;" ::: "memory");
    __syncthreads();                  // B region reusable
    if ((l & 3) == 0) {
        #pragma unroll
        for (int s = 0; s < 8; ++s) {
            int mt = s >> 1, half = s & 1;
            int m = mw * 64 + mt * 16 + half * 8 + (l >> 2);
            fbd[wn * 128 + m] = bd[s];
            fbi[wn * 128 + m] = bi[s];
        }
    }
    __syncthreads();
    if (tid < 128) {
        float best = fbd[tid]; int bidx = fbi[tid];
        #pragma unroll
        for (int q = 1; q < 8; ++q) {
            float d = fbd[q * 128 + tid]; int i2 = fbi[q * 128 + tid];
            if (d < best || (d == best && i2 < bidx)) { best = d; bidx = i2; }
        }
        sbi[tid] = bidx;
    }
    __syncthreads();

    // ---- gather exact fp32 codes, write outputs, loss partial ----
    float lsum = 0.0f;
    #pragma unroll 4
    for (int rr = 0; rr < 32; ++rr) {
        int idx = rr * THREADS + tid;
        int s = idx >> 7, k = idx & (DIM - 1);
        int c = sbi[s];
        float q = g_ctr[(size_t)c * DIM + k];
        float x = inp[(size_t)(s0 + s) * DIM + k];
        float d = q - x;
        out[(size_t)(s0 + s) * DIM + k] = x + d;
        lsum = fmaf(d, d, lsum);
    }
    #pragma unroll
    for (int o = 16; o > 0; o >>= 1) lsum += __shfl_xor_sync(0xffffffffu, lsum, o);
    if (l == 0) wsum[w] = lsum;
    __syncthreads();
    if (tid == 0) {
        float s = 0.0f;
        #pragma unroll
        for (int i = 0; i < 16; ++i) s += wsum[i];
        atomicAdd(&g_loss, s);
    }
}

// ---------------- kernel 4: loss = 1.25 * mean((q-x)^2) ----------------
__global__ void finalize_kernel(float* __restrict__ dst) {
    *dst = 1.25f * g_loss * (1.0f / (float)(M_TOTAL * DIM));
}

extern "C" void kernel_launch(void* const* d_in, const int* in_sizes, int n_in,
                              void* d_out, int out_size) {
    const float* inp = (const float*)d_in[0];
    const float* cm  = (const float*)d_in[1];
    if (n_in >= 2 && in_sizes[0] == DIM * NCODES && in_sizes[1] == M_TOTAL * DIM) {
        inp = (const float*)d_in[1];
        cm  = (const float*)d_in[0];
    }
    float* out = (float*)d_out;

    cudaFuncSetAttribute(vq_main_kernel,
                         cudaFuncAttributeMaxDynamicSharedMemorySize, SMEM_TOTAL);

    init_kernel<<<(NPAD2 + 255) / 256, 256>>>();
    trans_kernel<<<dim3(NPAD2 / 32, DIM / 32), dim3(32, 8)>>>(cm);
    pack_kernel<<<(int)(((size_t)NBUFS * BUF_U32) / 256), 256>>>(cm);
    vq_main_kernel<<<M_TOTAL / MTILE, THREADS, SMEM_TOTAL>>>(inp, out);
    if (out_size > M_TOTAL * DIM) {
        finalize_kernel<<<1, 1>>>(out + M_TOTAL * DIM);
    }
}